// round 16
// baseline (speedup 1.0000x reference)
#include <cuda_runtime.h>
#include <cuda_fp16.h>
#include <cstdint>
#include <math.h>

#define NN   65536
#define DD   256
#define HH   8
#define DKK  32
#define DFFv 1024
#define E1v  1048576
#define E2v  524288
#define EPSv 1e-5f
#define SCALEv 0.17677669529663687f  // 1/sqrt(32)
#define QKVS 768

// ------------------------- scratch (static device globals) -------------------------
__device__ __half g_qkvh[(size_t)NN * QKVS];
__device__ __half g_qkvh2[(size_t)NN * QKVS];
__device__ __half g_akh[32000];
__device__ __half g_agg[NN * DD];
__device__ float  g_h1[NN * DD];
__device__ __half g_h1r[NN * DD];
__device__ __half g_hr[NN * DD];
__device__ __half g_memr[NN * DD];
__device__ __half g_ffn[(size_t)NN * DFFv];
__device__ __half g_wqkv0[DD * QKVS];
__device__ __half g_wqkv1[DD * QKVS];
__device__ __half g_wo0r[DD * DD];
__device__ __half g_wo1r[DD * DD];
__device__ __half g_wf1r[DD * DFFv];
__device__ __half g_wf2r[DFFv * DD];
__device__ int    g_cnt[NN];
__device__ int    g_wr[NN];
__device__ int    g_rowptr[NN + 1];
__device__ int    g_srcs[E1v];
__device__ int    g_ets[E1v];
__device__ int    g_cnt2[NN];
__device__ int    g_wr2[NN];
__device__ int    g_rowptr2[NN + 1];
__device__ int    g_srcs2[E2v];

// ------------------------- helpers -------------------------
__device__ __forceinline__ void cp16(void* smem, const void* g) {
    unsigned saddr = (unsigned)__cvta_generic_to_shared(smem);
    asm volatile("cp.async.cg.shared.global [%0], [%1], 16;" :: "r"(saddr), "l"(g));
}
#define CP_COMMIT() asm volatile("cp.async.commit_group;")
#define CP_WAIT1()  asm volatile("cp.async.wait_group 1;")
#define CP_WAIT0()  asm volatile("cp.async.wait_group 0;")

#define MMA_F16(acc, a0, a1, a2, a3, b0, b1) \
    asm volatile( \
        "mma.sync.aligned.m16n8k16.row.col.f32.f16.f16.f32 " \
        "{%0,%1,%2,%3}, {%4,%5,%6,%7}, {%8,%9}, {%0,%1,%2,%3};" \
        : "+f"((acc)[0]), "+f"((acc)[1]), "+f"((acc)[2]), "+f"((acc)[3]) \
        : "r"(a0), "r"(a1), "r"(a2), "r"(a3), "r"(b0), "r"(b1))

// ------------------------- weight / activation prep ------------------------------
__global__ void pack_b_h(const float* __restrict__ W, __half* __restrict__ out,
                         int K, int Mm)
{
    int i = blockIdx.x * 256 + threadIdx.x;
    if (i >= K * Mm) return;
    int k = i / Mm, n = i % Mm;
    int blk = (k >> 4) * (Mm >> 3) + (n >> 3);
    int lane = (n & 7) * 4 + ((k & 7) >> 1);
    int pos = ((k & 15) >> 3) * 2 + (k & 1);
    out[blk * 128 + lane * 4 + pos] = __float2half_rn(W[i]);
}
__global__ void pack_qkv_b_h(const float* __restrict__ Wq, const float* __restrict__ Wk,
                             const float* __restrict__ Wv, __half* __restrict__ out)
{
    int i = blockIdx.x * 256 + threadIdx.x;          // DD*QKVS
    int k = i / QKVS, n = i % QKVS;
    const float* W = (n < 256) ? Wq : (n < 512 ? Wk : Wv);
    int blk = (k >> 4) * (QKVS >> 3) + (n >> 3);
    int lane = (n & 7) * 4 + ((k & 7) >> 1);
    int pos = ((k & 15) >> 3) * 2 + (k & 1);
    out[blk * 128 + lane * 4 + pos] = __float2half_rn(W[k * DD + (n & 255)]);
}
__global__ void round_half(const float* __restrict__ in, __half* __restrict__ out)
{
    int i = blockIdx.x * 256 + threadIdx.x;
    float4 v = reinterpret_cast<const float4*>(in)[i];
    __half2* o = reinterpret_cast<__half2*>(out) + i * 2;
    o[0] = __floats2half2_rn(v.x, v.y);
    o[1] = __floats2half2_rn(v.z, v.w);
}
__global__ void pack_ak(const float* __restrict__ ak, __half* __restrict__ out)
{
    int i = blockIdx.x * 256 + threadIdx.x;
    if (i < 32000) out[i] = __float2half_rn(ak[i]);
}

// ------------------------- 4-warp fp16 GEMM core (64x64 warp tiles) ---------------
#define ASTH 40                      // A smem row stride in halfs (80B)
#define ABYT (128 * 80)              // 10240 B
#define BBYT (32 * 128 * 2)          // 8192 B
#define STBY (ABYT + BBYT)           // 18432 B
#define SMEM_A (3 * STBY)            // 55296 B

template<bool RELU>
__device__ __forceinline__ void gemm_core4(
    const __half* __restrict__ A, const __half* __restrict__ B, __half* __restrict__ C,
    int Kk, int Mm, int bn, int Cs, int bnC, const float* __restrict__ bias)
{
    extern __shared__ char smb[];

    const int tid  = threadIdx.x;
    const int bm   = blockIdx.y * 128;
    const int wid  = tid >> 5;
    const int lane = tid & 31;
    const int wm   = (wid & 1) * 64;
    const int wn   = (wid >> 1) * 64;
    const int gid  = lane >> 2;
    const int tig  = lane & 3;

    float acc[4][8][4];
#pragma unroll
    for (int mt = 0; mt < 4; mt++)
#pragma unroll
        for (int nt = 0; nt < 8; nt++)
#pragma unroll
            for (int c = 0; c < 4; c++) acc[mt][nt][c] = 0.f;

    const int nIter = Kk / 32;
    const int mm8 = Mm >> 3;

    auto issue = [&](int it) {
        __half* As = reinterpret_cast<__half*>(smb + (it % 3) * STBY);
        char*   Bs = smb + (it % 3) * STBY + ABYT;
        const int k0 = it * 32;
#pragma unroll
        for (int i = 0; i < 4; i++) {
            int c = tid + 128 * i;
            int r = c >> 2, cc = (c & 3) * 8;
            cp16(As + r * ASTH + cc, A + (size_t)(bm + r) * Kk + k0 + cc);
        }
#pragma unroll
        for (int i = 0; i < 4; i++) {
            int c = tid + 128 * i;
            int ksb = c >> 8, rem = c & 255;
            const uint4* gsrc = reinterpret_cast<const uint4*>(B)
                + ((size_t)((k0 >> 4) + ksb) * mm8 + (bn >> 3)) * 16 + rem;
            cp16(Bs + (ksb * 256 + rem) * 16, gsrc);
        }
        CP_COMMIT();
    };

    issue(0);
    if (nIter > 1) issue(1);

    for (int it = 0; it < nIter; it++) {
        if (it + 1 < nIter) { CP_WAIT1(); } else { CP_WAIT0(); }
        __syncthreads();
        if (it + 2 < nIter) issue(it + 2);

        const __half* As = reinterpret_cast<const __half*>(smb + (it % 3) * STBY);
        const unsigned long long* Bs64 =
            reinterpret_cast<const unsigned long long*>(smb + (it % 3) * STBY + ABYT);

#pragma unroll
        for (int ks = 0; ks < 2; ks++) {
            const int kb = ks * 16;
            unsigned af[4][4];
#pragma unroll
            for (int mt = 0; mt < 4; mt++) {
                const int mr = wm + mt * 16 + gid;
                af[mt][0] = *reinterpret_cast<const unsigned*>(&As[mr * ASTH + kb + 2 * tig]);
                af[mt][1] = *reinterpret_cast<const unsigned*>(&As[(mr + 8) * ASTH + kb + 2 * tig]);
                af[mt][2] = *reinterpret_cast<const unsigned*>(&As[mr * ASTH + kb + 2 * tig + 8]);
                af[mt][3] = *reinterpret_cast<const unsigned*>(&As[(mr + 8) * ASTH + kb + 2 * tig + 8]);
            }
            unsigned bf[8][2];
#pragma unroll
            for (int nt = 0; nt < 8; nt++) {
                unsigned long long pr = Bs64[ks * 512 + (wn / 8 + nt) * 32 + lane];
                bf[nt][0] = (unsigned)pr;
                bf[nt][1] = (unsigned)(pr >> 32);
            }
#pragma unroll
            for (int mt = 0; mt < 4; mt++)
#pragma unroll
                for (int nt = 0; nt < 8; nt++)
                    MMA_F16(acc[mt][nt], af[mt][0], af[mt][1], af[mt][2], af[mt][3],
                            bf[nt][0], bf[nt][1]);
        }
    }

#pragma unroll
    for (int mt = 0; mt < 4; mt++) {
        const int row0 = bm + wm + mt * 16 + gid;
#pragma unroll
        for (int nt = 0; nt < 8; nt++) {
            const int col = bnC + wn + nt * 8 + 2 * tig;
            float b0 = 0.f, b1 = 0.f;
            if (bias) { b0 = bias[col]; b1 = bias[col + 1]; }
            float2 v0 = make_float2(acc[mt][nt][0] + b0, acc[mt][nt][1] + b1);
            float2 v1 = make_float2(acc[mt][nt][2] + b0, acc[mt][nt][3] + b1);
            if (RELU) {
                v0.x = fmaxf(v0.x, 0.f); v0.y = fmaxf(v0.y, 0.f);
                v1.x = fmaxf(v1.x, 0.f); v1.y = fmaxf(v1.y, 0.f);
            }
            *reinterpret_cast<__half2*>(&C[(size_t)row0 * Cs + col]) =
                __floats2half2_rn(v0.x, v0.y);
            *reinterpret_cast<__half2*>(&C[(size_t)(row0 + 8) * Cs + col]) =
                __floats2half2_rn(v1.x, v1.y);
        }
    }
}

__global__ __launch_bounds__(128, 2) void gemmA4(
    const __half* __restrict__ A, const __half* __restrict__ B, __half* __restrict__ C,
    int Kk, int Mm, const float* __restrict__ bias)
{
    gemm_core4<true>(A, B, C, Kk, Mm, blockIdx.x * 128, Mm, blockIdx.x * 128, bias);
}

// qkv projection into unified fp16 buffer (stride 768); bnoff selects column range
__global__ __launch_bounds__(128, 2) void gemm_qkvh(
    const __half* __restrict__ A, const __half* __restrict__ B, __half* __restrict__ C,
    int bnoff)
{
    const int bn = (blockIdx.x + bnoff) * 128;
    gemm_core4<false>(A, B, C, DD, QKVS, bn, QKVS, bn, nullptr);
}

// ------------------------- 8-warp LN-fused fp16 GEMM (64x256 block) ---------------
#define AWBY (64 * 80)               // 5120 B
#define BWBY (32 * 256 * 2)          // 16384 B
#define STBB (AWBY + BWBY)           // 21504 B
#define SMEM_B (2 * STBB)            // 43008 B

__global__ __launch_bounds__(256, 2) void gemmB_ln(
    const __half* __restrict__ A, const __half* __restrict__ B, float* __restrict__ C,
    int Kk, const float* __restrict__ bias,
    const float* __restrict__ resid, const float* __restrict__ lng,
    const float* __restrict__ lnb, __half* __restrict__ C2)
{
    extern __shared__ char smb[];

    const int tid  = threadIdx.x;
    const int bm   = blockIdx.y * 64;
    const int wid  = tid >> 5;
    const int lane = tid & 31;
    const int wm   = (wid & 1) * 32;
    const int wn   = (wid >> 1) * 64;
    const int gid  = lane >> 2;
    const int tig  = lane & 3;

    float acc[2][8][4];
#pragma unroll
    for (int mt = 0; mt < 2; mt++)
#pragma unroll
        for (int nt = 0; nt < 8; nt++)
#pragma unroll
            for (int c = 0; c < 4; c++) acc[mt][nt][c] = 0.f;

    const int nIter = Kk / 32;

    auto issue = [&](int it) {
        __half* As = reinterpret_cast<__half*>(smb + (it & 1) * STBB);
        char*   Bs = smb + (it & 1) * STBB + AWBY;
        const int k0 = it * 32;
        {
            int r = tid >> 2, cc = (tid & 3) * 8;
            cp16(As + r * ASTH + cc, A + (size_t)(bm + r) * Kk + k0 + cc);
        }
#pragma unroll
        for (int i = 0; i < 4; i++) {
            int c = tid + 256 * i;
            int ksb = c >> 9, rem = c & 511;
            const uint4* gsrc = reinterpret_cast<const uint4*>(B)
                + ((size_t)((k0 >> 4) + ksb) * 32) * 16 + rem;
            cp16(Bs + (ksb * 512 + rem) * 16, gsrc);
        }
        CP_COMMIT();
    };

    issue(0);
    if (nIter > 1) issue(1);

    for (int it = 0; it < nIter; it++) {
        if (it + 1 < nIter) { CP_WAIT1(); } else { CP_WAIT0(); }
        __syncthreads();

        const __half* As = reinterpret_cast<const __half*>(smb + (it & 1) * STBB);
        const unsigned long long* Bs64 =
            reinterpret_cast<const unsigned long long*>(smb + (it & 1) * STBB + AWBY);

#pragma unroll
        for (int ks = 0; ks < 2; ks++) {
            const int kb = ks * 16;
            unsigned af[2][4];
#pragma unroll
            for (int mt = 0; mt < 2; mt++) {
                const int mr = wm + mt * 16 + gid;
                af[mt][0] = *reinterpret_cast<const unsigned*>(&As[mr * ASTH + kb + 2 * tig]);
                af[mt][1] = *reinterpret_cast<const unsigned*>(&As[(mr + 8) * ASTH + kb + 2 * tig]);
                af[mt][2] = *reinterpret_cast<const unsigned*>(&As[mr * ASTH + kb + 2 * tig + 8]);
                af[mt][3] = *reinterpret_cast<const unsigned*>(&As[(mr + 8) * ASTH + kb + 2 * tig + 8]);
            }
            unsigned bf[8][2];
#pragma unroll
            for (int nt = 0; nt < 8; nt++) {
                unsigned long long pr = Bs64[ks * 1024 + (wn / 8 + nt) * 32 + lane];
                bf[nt][0] = (unsigned)pr;
                bf[nt][1] = (unsigned)(pr >> 32);
            }
#pragma unroll
            for (int mt = 0; mt < 2; mt++)
#pragma unroll
                for (int nt = 0; nt < 8; nt++)
                    MMA_F16(acc[mt][nt], af[mt][0], af[mt][1], af[mt][2], af[mt][3],
                            bf[nt][0], bf[nt][1]);
        }

        if (it + 2 < nIter) {
            __syncthreads();
            issue(it + 2);
        }
    }

    // ---------- fused residual + LayerNorm epilogue ----------
#pragma unroll
    for (int mt = 0; mt < 2; mt++) {
        const int r0 = bm + wm + mt * 16 + gid;
        const int r1 = r0 + 8;
#pragma unroll
        for (int nt = 0; nt < 8; nt++) {
            const int col = wn + nt * 8 + 2 * tig;
            float b0 = 0.f, b1 = 0.f;
            if (bias) { b0 = bias[col]; b1 = bias[col + 1]; }
            float2 xa = *reinterpret_cast<const float2*>(&resid[(size_t)r0 * 256 + col]);
            float2 xb = *reinterpret_cast<const float2*>(&resid[(size_t)r1 * 256 + col]);
            acc[mt][nt][0] += b0 + xa.x; acc[mt][nt][1] += b1 + xa.y;
            acc[mt][nt][2] += b0 + xb.x; acc[mt][nt][3] += b1 + xb.y;
        }
    }

    __syncthreads();
    float* sums  = reinterpret_cast<float*>(smb);
    float* sumsq = sums + 64;
    if (tid < 64) { sums[tid] = 0.f; sumsq[tid] = 0.f; }
    __syncthreads();

#pragma unroll
    for (int mt = 0; mt < 2; mt++) {
        float sA = 0.f, qA = 0.f, sB = 0.f, qB = 0.f;
#pragma unroll
        for (int nt = 0; nt < 8; nt++) {
            sA += acc[mt][nt][0] + acc[mt][nt][1];
            qA += acc[mt][nt][0] * acc[mt][nt][0] + acc[mt][nt][1] * acc[mt][nt][1];
            sB += acc[mt][nt][2] + acc[mt][nt][3];
            qB += acc[mt][nt][2] * acc[mt][nt][2] + acc[mt][nt][3] * acc[mt][nt][3];
        }
        sA += __shfl_xor_sync(0xffffffffu, sA, 1); sA += __shfl_xor_sync(0xffffffffu, sA, 2);
        qA += __shfl_xor_sync(0xffffffffu, qA, 1); qA += __shfl_xor_sync(0xffffffffu, qA, 2);
        sB += __shfl_xor_sync(0xffffffffu, sB, 1); sB += __shfl_xor_sync(0xffffffffu, sB, 2);
        qB += __shfl_xor_sync(0xffffffffu, qB, 1); qB += __shfl_xor_sync(0xffffffffu, qB, 2);
        if (tig == 0) {
            const int lr = wm + mt * 16 + gid;
            atomicAdd(&sums[lr], sA);     atomicAdd(&sumsq[lr], qA);
            atomicAdd(&sums[lr + 8], sB); atomicAdd(&sumsq[lr + 8], qB);
        }
    }
    __syncthreads();

    const float inv = 1.f / 256.f;
#pragma unroll
    for (int mt = 0; mt < 2; mt++) {
        const int lr0 = wm + mt * 16 + gid;
        const int lr1 = lr0 + 8;
        const float mu0 = sums[lr0] * inv;
        const float mu1 = sums[lr1] * inv;
        const float rs0 = rsqrtf(sumsq[lr0] * inv - mu0 * mu0 + EPSv);
        const float rs1 = rsqrtf(sumsq[lr1] * inv - mu1 * mu1 + EPSv);
        const int r0 = bm + lr0, r1 = bm + lr1;
#pragma unroll
        for (int nt = 0; nt < 8; nt++) {
            const int col = wn + nt * 8 + 2 * tig;
            float2 gv = *reinterpret_cast<const float2*>(&lng[col]);
            float2 bv = *reinterpret_cast<const float2*>(&lnb[col]);
            float2 o0 = make_float2((acc[mt][nt][0] - mu0) * rs0 * gv.x + bv.x,
                                    (acc[mt][nt][1] - mu0) * rs0 * gv.y + bv.y);
            float2 o1 = make_float2((acc[mt][nt][2] - mu1) * rs1 * gv.x + bv.x,
                                    (acc[mt][nt][3] - mu1) * rs1 * gv.y + bv.y);
            *reinterpret_cast<float2*>(&C[(size_t)r0 * 256 + col]) = o0;
            *reinterpret_cast<float2*>(&C[(size_t)r1 * 256 + col]) = o1;
            if (C2) {
                *reinterpret_cast<__half2*>(&C2[(size_t)r0 * 256 + col]) =
                    __floats2half2_rn(o0.x, o0.y);
                *reinterpret_cast<__half2*>(&C2[(size_t)r1 * 256 + col]) =
                    __floats2half2_rn(o1.x, o1.y);
            }
        }
    }
}

// ------------------------- CSR build ----------------------------------------------
__global__ void hist_kernel(const int* __restrict__ dst, int* __restrict__ cnt, int E)
{
    int e = blockIdx.x * blockDim.x + threadIdx.x;
    if (e < E) atomicAdd(&cnt[dst[e]], 1);
}

__global__ __launch_bounds__(1024) void scan64k(
    const int* __restrict__ cnt, int* __restrict__ rowptr, int* __restrict__ wr)
{
    __shared__ int ss[1024];
    const int tid = threadIdx.x;
    const int base = tid * 64;
    int s = 0;
#pragma unroll
    for (int i = 0; i < 64; i++) s += cnt[base + i];
    ss[tid] = s;
    __syncthreads();
#pragma unroll
    for (int off = 1; off < 1024; off <<= 1) {
        int t = (tid >= off) ? ss[tid - off] : 0;
        __syncthreads();
        ss[tid] += t;
        __syncthreads();
    }
    int run = ss[tid] - s;
    for (int i = 0; i < 64; i++) {
        rowptr[base + i] = run;
        wr[base + i] = run;
        run += cnt[base + i];
    }
    if (tid == 1023) rowptr[NN] = run;
}

__global__ void scatter_csr(const int* __restrict__ src, const int* __restrict__ dst,
                            const int* __restrict__ et, int* __restrict__ wr,
                            int* __restrict__ srcs, int* __restrict__ ets, int E)
{
    int e = blockIdx.x * blockDim.x + threadIdx.x;
    if (e >= E) return;
    int pos = atomicAdd(&wr[dst[e]], 1);
    srcs[pos] = src[e];
    if (et) ets[pos] = et[e];
}

// ------------------------- per-destination attention (all-fp16 gather) ------------
template<bool HASAK>
__global__ void dst_attn(const __half* __restrict__ qkv, const __half* __restrict__ akh,
                         const int* __restrict__ srcs, const int* __restrict__ ets,
                         const int* __restrict__ rowptr, __half* __restrict__ agg)
{
    const int node = (blockIdx.x * blockDim.x + threadIdx.x) >> 5;
    const int lane = threadIdx.x & 31;
    uint4 qraw = *reinterpret_cast<const uint4*>(qkv + (size_t)node * QKVS + lane * 8);
    const __half2* qh = reinterpret_cast<const __half2*>(&qraw);
    const float2 qA = __half22float2(qh[0]);
    const float2 qB = __half22float2(qh[1]);
    const float2 qC = __half22float2(qh[2]);
    const float2 qD = __half22float2(qh[3]);
    const int beg = rowptr[node], end = rowptr[node + 1];

    float4 acc0 = make_float4(0.f, 0.f, 0.f, 0.f);
    float4 acc1 = make_float4(0.f, 0.f, 0.f, 0.f);
    float den = 0.f;

#pragma unroll 4
    for (int j = beg; j < end; j++) {
        const int s = srcs[j];
        const __half* kvrow = qkv + (size_t)s * QKVS;
        uint4 kraw = *reinterpret_cast<const uint4*>(kvrow + 256 + lane * 8);
        const __half2* kh = reinterpret_cast<const __half2*>(&kraw);
        float2 kA = __half22float2(kh[0]);
        float2 kB = __half22float2(kh[1]);
        float2 kC = __half22float2(kh[2]);
        float2 kD = __half22float2(kh[3]);
        if (HASAK) {
            uint4 araw = *reinterpret_cast<const uint4*>(
                akh + (size_t)ets[j] * DKK + (lane & 3) * 8);
            const __half2* ah = reinterpret_cast<const __half2*>(&araw);
            float2 aA = __half22float2(ah[0]);
            float2 aB = __half22float2(ah[1]);
            float2 aC = __half22float2(ah[2]);
            float2 aD = __half22float2(ah[3]);
            kA.x += aA.x; kA.y += aA.y; kB.x += aB.x; kB.y += aB.y;
            kC.x += aC.x; kC.y += aC.y; kD.x += aD.x; kD.y += aD.y;
        }
        float p = kA.x * qA.x + kA.y * qA.y + kB.x * qB.x + kB.y * qB.y
                + kC.x * qC.x + kC.y * qC.y + kD.x * qD.x + kD.y * qD.y;
        p += __shfl_xor_sync(0xffffffffu, p, 1);
        p += __shfl_xor_sync(0xffffffffu, p, 2);
        const float w = __expf(p * SCALEv);
        uint4 vraw = *reinterpret_cast<const uint4*>(kvrow + 512 + lane * 8);
        const __half2* vh = reinterpret_cast<const __half2*>(&vraw);
        float2 vA = __half22float2(vh[0]);
        float2 vB = __half22float2(vh[1]);
        float2 vC = __half22float2(vh[2]);
        float2 vD = __half22float2(vh[3]);
        acc0.x += w * vA.x; acc0.y += w * vA.y; acc0.z += w * vB.x; acc0.w += w * vB.y;
        acc1.x += w * vC.x; acc1.y += w * vC.y; acc1.z += w * vD.x; acc1.w += w * vD.y;
        den += w;
    }
    const float r = den > 0.f ? __frcp_rn(den) : 0.f;
    __half2* outp = reinterpret_cast<__half2*>(agg + (size_t)node * DD + lane * 8);
    outp[0] = __floats2half2_rn(acc0.x * r, acc0.y * r);
    outp[1] = __floats2half2_rn(acc0.z * r, acc0.w * r);
    outp[2] = __floats2half2_rn(acc1.x * r, acc1.y * r);
    outp[3] = __floats2half2_rn(acc1.z * r, acc1.w * r);
}

// ------------------------- host launch -------------------------
extern "C" void kernel_launch(void* const* d_in, const int* in_sizes, int n_in,
                              void* d_out, int out_size)
{
    const float *h = nullptr, *mem = nullptr, *ak = nullptr, *bf1 = nullptr;
    const float *W[8] = {nullptr};
    const float *Wf[2] = {nullptr};
    const float *v256[8] = {nullptr};
    const int *src_intra = nullptr, *dst_intra = nullptr, *etype = nullptr;
    const int *src_inter = nullptr, *dst_inter = nullptr;
    int c16 = 0, c1m = 0, c512k = 0, c64k = 0, c262k = 0, c256 = 0;

    for (int i = 0; i < n_in; i++) {
        int sz = in_sizes[i];
        void* p = d_in[i];
        if (sz == 16777216)      { if (c16 == 0) h = (const float*)p; else mem = (const float*)p; c16++; }
        else if (sz == 1048576)  { if (c1m == 0) src_intra = (const int*)p;
                                   else if (c1m == 1) dst_intra = (const int*)p;
                                   else etype = (const int*)p; c1m++; }
        else if (sz == 524288)   { if (c512k == 0) src_inter = (const int*)p; else dst_inter = (const int*)p; c512k++; }
        else if (sz == 65536)    { if (c64k < 8) W[c64k] = (const float*)p; c64k++; }
        else if (sz == 32000)    { ak = (const float*)p; }
        else if (sz == 262144)   { if (c262k < 2) Wf[c262k] = (const float*)p; c262k++; }
        else if (sz == 1024)     { bf1 = (const float*)p; }
        else if (sz == 256)      { if (c256 < 8) v256[c256] = (const float*)p; c256++; }
    }
    const float *ln0_g = v256[0], *ln0_b = v256[1];
    const float *ln1_g = v256[2], *ln1_b = v256[3];
    const float *ln2_g = v256[4], *ln2_b = v256[5];
    const float *bf2   = v256[6];

    float *h1;
    __half *qkvh, *qkvh2, *akh, *agg, *h1r, *hr, *memr, *ffn;
    __half *wqkv0, *wqkv1, *wo0r, *wo1r, *wf1r, *wf2r;
    int *cnt, *wr, *rowptr, *srcs, *ets;
    int *cnt2, *wr2, *rowptr2, *srcs2;
    cudaGetSymbolAddress((void**)&qkvh,   g_qkvh);
    cudaGetSymbolAddress((void**)&qkvh2,  g_qkvh2);
    cudaGetSymbolAddress((void**)&akh,    g_akh);
    cudaGetSymbolAddress((void**)&agg,    g_agg);
    cudaGetSymbolAddress((void**)&h1,     g_h1);
    cudaGetSymbolAddress((void**)&h1r,    g_h1r);
    cudaGetSymbolAddress((void**)&hr,     g_hr);
    cudaGetSymbolAddress((void**)&memr,   g_memr);
    cudaGetSymbolAddress((void**)&ffn,    g_ffn);
    cudaGetSymbolAddress((void**)&wqkv0,  g_wqkv0);
    cudaGetSymbolAddress((void**)&wqkv1,  g_wqkv1);
    cudaGetSymbolAddress((void**)&wo0r,   g_wo0r);
    cudaGetSymbolAddress((void**)&wo1r,   g_wo1r);
    cudaGetSymbolAddress((void**)&wf1r,   g_wf1r);
    cudaGetSymbolAddress((void**)&wf2r,   g_wf2r);
    cudaGetSymbolAddress((void**)&cnt,    g_cnt);
    cudaGetSymbolAddress((void**)&wr,     g_wr);
    cudaGetSymbolAddress((void**)&rowptr, g_rowptr);
    cudaGetSymbolAddress((void**)&srcs,   g_srcs);
    cudaGetSymbolAddress((void**)&ets,    g_ets);
    cudaGetSymbolAddress((void**)&cnt2,   g_cnt2);
    cudaGetSymbolAddress((void**)&wr2,    g_wr2);
    cudaGetSymbolAddress((void**)&rowptr2,g_rowptr2);
    cudaGetSymbolAddress((void**)&srcs2,  g_srcs2);

    float* out = (float*)d_out;

    cudaFuncSetAttribute(gemmA4,    cudaFuncAttributeMaxDynamicSharedMemorySize, SMEM_A);
    cudaFuncSetAttribute(gemm_qkvh, cudaFuncAttributeMaxDynamicSharedMemorySize, SMEM_A);
    cudaFuncSetAttribute(gemmB_ln,  cudaFuncAttributeMaxDynamicSharedMemorySize, SMEM_B);

    // ---------------- stream fork ----------------
    cudaStream_t s2;
    cudaStreamCreateWithFlags(&s2, cudaStreamNonBlocking);
    cudaEvent_t evRoot, evCSR1, evPacks, evS2;
    cudaEventCreateWithFlags(&evRoot,  cudaEventDisableTiming);
    cudaEventCreateWithFlags(&evCSR1,  cudaEventDisableTiming);
    cudaEventCreateWithFlags(&evPacks, cudaEventDisableTiming);
    cudaEventCreateWithFlags(&evS2,    cudaEventDisableTiming);

    cudaEventRecord(evRoot, 0);
    cudaStreamWaitEvent(s2, evRoot, 0);

    // ---- side stream: ak pack, CSR builds, all remaining prep, stage-2 KV GEMM ----
    pack_ak<<<125, 256, 0, s2>>>(ak, akh);
    cudaMemsetAsync(cnt,  0, NN * sizeof(int), s2);
    cudaMemsetAsync(cnt2, 0, NN * sizeof(int), s2);
    hist_kernel<<<E1v / 256, 256, 0, s2>>>(dst_intra, cnt, E1v);
    scan64k<<<1, 1024, 0, s2>>>(cnt, rowptr, wr);
    scatter_csr<<<E1v / 256, 256, 0, s2>>>(src_intra, dst_intra, etype, wr, srcs, ets, E1v);
    cudaEventRecord(evCSR1, s2);
    hist_kernel<<<E2v / 256, 256, 0, s2>>>(dst_inter, cnt2, E2v);
    scan64k<<<1, 1024, 0, s2>>>(cnt2, rowptr2, wr2);
    scatter_csr<<<E2v / 256, 256, 0, s2>>>(src_inter, dst_inter, nullptr, wr2, srcs2, nullptr, E2v);
    round_half<<<NN * DD / 4 / 256, 256, 0, s2>>>(mem, memr);
    pack_qkv_b_h<<<DD * QKVS / 256, 256, 0, s2>>>(W[4], W[5], W[6], wqkv1);
    pack_b_h<<<DD * DD / 256, 256, 0, s2>>>(W[3], wo0r, DD, DD);
    pack_b_h<<<DD * DD / 256, 256, 0, s2>>>(W[7], wo1r, DD, DD);
    pack_b_h<<<DD * DFFv / 256, 256, 0, s2>>>(Wf[0], wf1r, DD, DFFv);
    pack_b_h<<<DFFv * DD / 256, 256, 0, s2>>>(Wf[1], wf2r, DFFv, DD);
    cudaEventRecord(evPacks, s2);
    // stage-2 K/V projection (cols 256..767 of qkvh2); independent of stage 1
    gemm_qkvh<<<dim3(4, NN / 128), 128, SMEM_A, s2>>>(memr, wqkv1, qkvh2, 2);
    cudaEventRecord(evS2, s2);

    // ---- main stream: minimal prep, then critical path ----
    round_half<<<NN * DD / 4 / 256, 256>>>(h, hr);
    pack_qkv_b_h<<<DD * QKVS / 256, 256>>>(W[0], W[1], W[2], wqkv0);

    dim3 gLN(1, NN / 64);
    dim3 gF1(DFFv / 128, NN / 128);
    const int ATT_BLKS = NN / 8;

    // stage 1: intra attention
    gemm_qkvh<<<dim3(6, NN / 128), 128, SMEM_A>>>(hr, wqkv0, qkvh, 0);
    cudaStreamWaitEvent(0, evCSR1, 0);
    dst_attn<true><<<ATT_BLKS, 256>>>(qkvh, akh, srcs, ets, rowptr, agg);
    cudaStreamWaitEvent(0, evPacks, 0);
    gemmB_ln<<<gLN, 256, SMEM_B>>>(agg, wo0r, h1, DD, nullptr, h, ln0_g, ln0_b, h1r);

    // stage 2: inter attention (q cols 0..255 of qkvh2; kv done on side stream)
    gemm_qkvh<<<dim3(2, NN / 128), 128, SMEM_A>>>(h1r, wqkv1, qkvh2, 0);
    cudaStreamWaitEvent(0, evS2, 0);
    dst_attn<false><<<ATT_BLKS, 256>>>(qkvh2, nullptr, srcs2, nullptr, rowptr2, agg);
    gemmB_ln<<<gLN, 256, SMEM_B>>>(agg, wo1r, h1, DD, nullptr, h1, ln1_g, ln1_b, h1r);

    // FFN + final norm
    gemmA4<<<gF1, 128, SMEM_A>>>(h1r, wf1r, ffn, DD, DFFv, bf1);
    gemmB_ln<<<gLN, 256, SMEM_B>>>(ffn, wf2r, out, DFFv, bf2, h1, ln2_g, ln2_b, nullptr);
}

// round 17
// speedup vs baseline: 1.2621x; 1.2621x over previous
#include <cuda_runtime.h>
#include <cuda_fp16.h>
#include <cstdint>
#include <math.h>

#define NN   65536
#define DD   256
#define HH   8
#define DKK  32
#define DFFv 1024
#define E1v  1048576
#define E2v  524288
#define EPSv 1e-5f
#define SCALEv 0.17677669529663687f  // 1/sqrt(32)
#define QKVS 768

// ------------------------- scratch (static device globals) -------------------------
__device__ float  g_q[(size_t)NN * DD];
__device__ float  g_q2[(size_t)NN * DD];
__device__ __half g_kv[(size_t)NN * 512];
__device__ __half g_kv2[(size_t)NN * 512];
__device__ __half g_akh[32000];
__device__ __half g_agg[NN * DD];
__device__ float  g_h1[NN * DD];
__device__ __half g_h1r[NN * DD];
__device__ __half g_hr[NN * DD];
__device__ __half g_memr[NN * DD];
__device__ __half g_ffn[(size_t)NN * DFFv];
__device__ __half g_wqkv0[DD * QKVS];
__device__ __half g_wqkv1[DD * QKVS];
__device__ __half g_wo0r[DD * DD];
__device__ __half g_wo1r[DD * DD];
__device__ __half g_wf1r[DD * DFFv];
__device__ __half g_wf2r[DFFv * DD];
__device__ int    g_cnt[NN];
__device__ int    g_wr[NN];
__device__ int    g_rowptr[NN + 1];
__device__ int    g_srcs[E1v];
__device__ int    g_ets[E1v];
__device__ int    g_cnt2[NN];
__device__ int    g_wr2[NN];
__device__ int    g_rowptr2[NN + 1];
__device__ int    g_srcs2[E2v];

// ------------------------- helpers -------------------------
__device__ __forceinline__ void cp16(void* smem, const void* g) {
    unsigned saddr = (unsigned)__cvta_generic_to_shared(smem);
    asm volatile("cp.async.cg.shared.global [%0], [%1], 16;" :: "r"(saddr), "l"(g));
}
#define CP_COMMIT() asm volatile("cp.async.commit_group;")
#define CP_WAIT1()  asm volatile("cp.async.wait_group 1;")
#define CP_WAIT0()  asm volatile("cp.async.wait_group 0;")

#define MMA_F16(acc, a0, a1, a2, a3, b0, b1) \
    asm volatile( \
        "mma.sync.aligned.m16n8k16.row.col.f32.f16.f16.f32 " \
        "{%0,%1,%2,%3}, {%4,%5,%6,%7}, {%8,%9}, {%0,%1,%2,%3};" \
        : "+f"((acc)[0]), "+f"((acc)[1]), "+f"((acc)[2]), "+f"((acc)[3]) \
        : "r"(a0), "r"(a1), "r"(a2), "r"(a3), "r"(b0), "r"(b1))

// ------------------------- weight / activation prep ------------------------------
__global__ void pack_b_h(const float* __restrict__ W, __half* __restrict__ out,
                         int K, int Mm)
{
    int i = blockIdx.x * 256 + threadIdx.x;
    if (i >= K * Mm) return;
    int k = i / Mm, n = i % Mm;
    int blk = (k >> 4) * (Mm >> 3) + (n >> 3);
    int lane = (n & 7) * 4 + ((k & 7) >> 1);
    int pos = ((k & 15) >> 3) * 2 + (k & 1);
    out[blk * 128 + lane * 4 + pos] = __float2half_rn(W[i]);
}
__global__ void pack_qkv_b_h(const float* __restrict__ Wq, const float* __restrict__ Wk,
                             const float* __restrict__ Wv, __half* __restrict__ out)
{
    int i = blockIdx.x * 256 + threadIdx.x;          // DD*QKVS
    int k = i / QKVS, n = i % QKVS;
    const float* W = (n < 256) ? Wq : (n < 512 ? Wk : Wv);
    int blk = (k >> 4) * (QKVS >> 3) + (n >> 3);
    int lane = (n & 7) * 4 + ((k & 7) >> 1);
    int pos = ((k & 15) >> 3) * 2 + (k & 1);
    out[blk * 128 + lane * 4 + pos] = __float2half_rn(W[k * DD + (n & 255)]);
}
__global__ void round_half(const float* __restrict__ in, __half* __restrict__ out)
{
    int i = blockIdx.x * 256 + threadIdx.x;
    float4 v = reinterpret_cast<const float4*>(in)[i];
    __half2* o = reinterpret_cast<__half2*>(out) + i * 2;
    o[0] = __floats2half2_rn(v.x, v.y);
    o[1] = __floats2half2_rn(v.z, v.w);
}
__global__ void pack_ak(const float* __restrict__ ak, __half* __restrict__ out)
{
    int i = blockIdx.x * 256 + threadIdx.x;
    if (i < 32000) out[i] = __float2half_rn(ak[i]);
}

// ------------------------- 4-warp fp16 GEMM core (64x64 warp tiles) ---------------
#define ASTH 40                      // A smem row stride in halfs (80B)
#define ABYT (128 * 80)              // 10240 B
#define BBYT (32 * 128 * 2)          // 8192 B
#define STBY (ABYT + BBYT)           // 18432 B
#define SMEM_A (3 * STBY)            // 55296 B

template<bool OUTHALF, bool RELU>
__device__ __forceinline__ void gemm_core4(
    const __half* __restrict__ A, const __half* __restrict__ B, void* __restrict__ Cv,
    int Kk, int Mm, int bn, int Cs, int bnC, const float* __restrict__ bias)
{
    extern __shared__ char smb[];

    const int tid  = threadIdx.x;
    const int bm   = blockIdx.y * 128;
    const int wid  = tid >> 5;
    const int lane = tid & 31;
    const int wm   = (wid & 1) * 64;
    const int wn   = (wid >> 1) * 64;
    const int gid  = lane >> 2;
    const int tig  = lane & 3;

    float acc[4][8][4];
#pragma unroll
    for (int mt = 0; mt < 4; mt++)
#pragma unroll
        for (int nt = 0; nt < 8; nt++)
#pragma unroll
            for (int c = 0; c < 4; c++) acc[mt][nt][c] = 0.f;

    const int nIter = Kk / 32;
    const int mm8 = Mm >> 3;

    auto issue = [&](int it) {
        __half* As = reinterpret_cast<__half*>(smb + (it % 3) * STBY);
        char*   Bs = smb + (it % 3) * STBY + ABYT;
        const int k0 = it * 32;
#pragma unroll
        for (int i = 0; i < 4; i++) {
            int c = tid + 128 * i;
            int r = c >> 2, cc = (c & 3) * 8;
            cp16(As + r * ASTH + cc, A + (size_t)(bm + r) * Kk + k0 + cc);
        }
#pragma unroll
        for (int i = 0; i < 4; i++) {
            int c = tid + 128 * i;
            int ksb = c >> 8, rem = c & 255;
            const uint4* gsrc = reinterpret_cast<const uint4*>(B)
                + ((size_t)((k0 >> 4) + ksb) * mm8 + (bn >> 3)) * 16 + rem;
            cp16(Bs + (ksb * 256 + rem) * 16, gsrc);
        }
        CP_COMMIT();
    };

    issue(0);
    if (nIter > 1) issue(1);

    for (int it = 0; it < nIter; it++) {
        if (it + 1 < nIter) { CP_WAIT1(); } else { CP_WAIT0(); }
        __syncthreads();
        if (it + 2 < nIter) issue(it + 2);

        const __half* As = reinterpret_cast<const __half*>(smb + (it % 3) * STBY);
        const unsigned long long* Bs64 =
            reinterpret_cast<const unsigned long long*>(smb + (it % 3) * STBY + ABYT);

#pragma unroll
        for (int ks = 0; ks < 2; ks++) {
            const int kb = ks * 16;
            unsigned af[4][4];
#pragma unroll
            for (int mt = 0; mt < 4; mt++) {
                const int mr = wm + mt * 16 + gid;
                af[mt][0] = *reinterpret_cast<const unsigned*>(&As[mr * ASTH + kb + 2 * tig]);
                af[mt][1] = *reinterpret_cast<const unsigned*>(&As[(mr + 8) * ASTH + kb + 2 * tig]);
                af[mt][2] = *reinterpret_cast<const unsigned*>(&As[mr * ASTH + kb + 2 * tig + 8]);
                af[mt][3] = *reinterpret_cast<const unsigned*>(&As[(mr + 8) * ASTH + kb + 2 * tig + 8]);
            }
            unsigned bf[8][2];
#pragma unroll
            for (int nt = 0; nt < 8; nt++) {
                unsigned long long pr = Bs64[ks * 512 + (wn / 8 + nt) * 32 + lane];
                bf[nt][0] = (unsigned)pr;
                bf[nt][1] = (unsigned)(pr >> 32);
            }
#pragma unroll
            for (int mt = 0; mt < 4; mt++)
#pragma unroll
                for (int nt = 0; nt < 8; nt++)
                    MMA_F16(acc[mt][nt], af[mt][0], af[mt][1], af[mt][2], af[mt][3],
                            bf[nt][0], bf[nt][1]);
        }
    }

#pragma unroll
    for (int mt = 0; mt < 4; mt++) {
        const int row0 = bm + wm + mt * 16 + gid;
#pragma unroll
        for (int nt = 0; nt < 8; nt++) {
            const int col = bnC + wn + nt * 8 + 2 * tig;
            float b0 = 0.f, b1 = 0.f;
            if (bias) { b0 = bias[col]; b1 = bias[col + 1]; }
            float2 v0 = make_float2(acc[mt][nt][0] + b0, acc[mt][nt][1] + b1);
            float2 v1 = make_float2(acc[mt][nt][2] + b0, acc[mt][nt][3] + b1);
            if (RELU) {
                v0.x = fmaxf(v0.x, 0.f); v0.y = fmaxf(v0.y, 0.f);
                v1.x = fmaxf(v1.x, 0.f); v1.y = fmaxf(v1.y, 0.f);
            }
            if (OUTHALF) {
                __half* C = (__half*)Cv;
                *reinterpret_cast<__half2*>(&C[(size_t)row0 * Cs + col]) =
                    __floats2half2_rn(v0.x, v0.y);
                *reinterpret_cast<__half2*>(&C[(size_t)(row0 + 8) * Cs + col]) =
                    __floats2half2_rn(v1.x, v1.y);
            } else {
                float* C = (float*)Cv;
                *reinterpret_cast<float2*>(&C[(size_t)row0 * Cs + col]) = v0;
                *reinterpret_cast<float2*>(&C[(size_t)(row0 + 8) * Cs + col]) = v1;
            }
        }
    }
}

__global__ __launch_bounds__(128, 2) void gemmA4(
    const __half* __restrict__ A, const __half* __restrict__ B, __half* __restrict__ C,
    int Kk, int Mm, const float* __restrict__ bias)
{
    gemm_core4<true, true>(A, B, C, Kk, Mm, blockIdx.x * 128, Mm, blockIdx.x * 128, bias);
}

// q projection: B cols [0,256) of packed qkv weight -> fp32 q buffer (stride 256)
__global__ __launch_bounds__(128, 2) void gemm_q4(
    const __half* __restrict__ A, const __half* __restrict__ B, float* __restrict__ C)
{
    const int bn = blockIdx.x * 128;
    gemm_core4<false, false>(A, B, C, DD, QKVS, bn, 256, bn, nullptr);
}

// kv projection: B cols [256,768) -> fp16 kv buffer (stride 512; k at 0, v at 256)
__global__ __launch_bounds__(128, 2) void gemm_kv4(
    const __half* __restrict__ A, const __half* __restrict__ B, __half* __restrict__ C)
{
    const int bn = (blockIdx.x + 2) * 128;
    gemm_core4<true, false>(A, B, C, DD, QKVS, bn, 512, bn - 256, nullptr);
}

// ------------------------- 8-warp LN-fused fp16 GEMM (64x256 block, 3-stage) ------
#define AWBY (64 * 80)               // 5120 B
#define BWBY (32 * 256 * 2)          // 16384 B
#define STBB (AWBY + BWBY)           // 21504 B
#define SMEM_B (3 * STBB)            // 64512 B

__global__ __launch_bounds__(256, 2) void gemmB_ln(
    const __half* __restrict__ A, const __half* __restrict__ B, float* __restrict__ C,
    int Kk, const float* __restrict__ bias,
    const float* __restrict__ resid, const float* __restrict__ lng,
    const float* __restrict__ lnb, __half* __restrict__ C2)
{
    extern __shared__ char smb[];

    const int tid  = threadIdx.x;
    const int bm   = blockIdx.y * 64;
    const int wid  = tid >> 5;
    const int lane = tid & 31;
    const int wm   = (wid & 1) * 32;
    const int wn   = (wid >> 1) * 64;
    const int gid  = lane >> 2;
    const int tig  = lane & 3;

    float acc[2][8][4];
#pragma unroll
    for (int mt = 0; mt < 2; mt++)
#pragma unroll
        for (int nt = 0; nt < 8; nt++)
#pragma unroll
            for (int c = 0; c < 4; c++) acc[mt][nt][c] = 0.f;

    const int nIter = Kk / 32;

    auto issue = [&](int it) {
        __half* As = reinterpret_cast<__half*>(smb + (it % 3) * STBB);
        char*   Bs = smb + (it % 3) * STBB + AWBY;
        const int k0 = it * 32;
        {
            int r = tid >> 2, cc = (tid & 3) * 8;
            cp16(As + r * ASTH + cc, A + (size_t)(bm + r) * Kk + k0 + cc);
        }
#pragma unroll
        for (int i = 0; i < 4; i++) {
            int c = tid + 256 * i;
            int ksb = c >> 9, rem = c & 511;
            const uint4* gsrc = reinterpret_cast<const uint4*>(B)
                + ((size_t)((k0 >> 4) + ksb) * 32) * 16 + rem;
            cp16(Bs + (ksb * 512 + rem) * 16, gsrc);
        }
        CP_COMMIT();
    };

    issue(0);
    if (nIter > 1) issue(1);

    for (int it = 0; it < nIter; it++) {
        if (it + 1 < nIter) { CP_WAIT1(); } else { CP_WAIT0(); }
        __syncthreads();
        if (it + 2 < nIter) issue(it + 2);

        const __half* As = reinterpret_cast<const __half*>(smb + (it % 3) * STBB);
        const unsigned long long* Bs64 =
            reinterpret_cast<const unsigned long long*>(smb + (it % 3) * STBB + AWBY);

#pragma unroll
        for (int ks = 0; ks < 2; ks++) {
            const int kb = ks * 16;
            unsigned af[2][4];
#pragma unroll
            for (int mt = 0; mt < 2; mt++) {
                const int mr = wm + mt * 16 + gid;
                af[mt][0] = *reinterpret_cast<const unsigned*>(&As[mr * ASTH + kb + 2 * tig]);
                af[mt][1] = *reinterpret_cast<const unsigned*>(&As[(mr + 8) * ASTH + kb + 2 * tig]);
                af[mt][2] = *reinterpret_cast<const unsigned*>(&As[mr * ASTH + kb + 2 * tig + 8]);
                af[mt][3] = *reinterpret_cast<const unsigned*>(&As[(mr + 8) * ASTH + kb + 2 * tig + 8]);
            }
            unsigned bf[8][2];
#pragma unroll
            for (int nt = 0; nt < 8; nt++) {
                unsigned long long pr = Bs64[ks * 1024 + (wn / 8 + nt) * 32 + lane];
                bf[nt][0] = (unsigned)pr;
                bf[nt][1] = (unsigned)(pr >> 32);
            }
#pragma unroll
            for (int mt = 0; mt < 2; mt++)
#pragma unroll
                for (int nt = 0; nt < 8; nt++)
                    MMA_F16(acc[mt][nt], af[mt][0], af[mt][1], af[mt][2], af[mt][3],
                            bf[nt][0], bf[nt][1]);
        }
    }

    // ---------- fused residual + LayerNorm epilogue ----------
#pragma unroll
    for (int mt = 0; mt < 2; mt++) {
        const int r0 = bm + wm + mt * 16 + gid;
        const int r1 = r0 + 8;
#pragma unroll
        for (int nt = 0; nt < 8; nt++) {
            const int col = wn + nt * 8 + 2 * tig;
            float b0 = 0.f, b1 = 0.f;
            if (bias) { b0 = bias[col]; b1 = bias[col + 1]; }
            float2 xa = *reinterpret_cast<const float2*>(&resid[(size_t)r0 * 256 + col]);
            float2 xb = *reinterpret_cast<const float2*>(&resid[(size_t)r1 * 256 + col]);
            acc[mt][nt][0] += b0 + xa.x; acc[mt][nt][1] += b1 + xa.y;
            acc[mt][nt][2] += b0 + xb.x; acc[mt][nt][3] += b1 + xb.y;
        }
    }

    __syncthreads();
    float* sums  = reinterpret_cast<float*>(smb);
    float* sumsq = sums + 64;
    if (tid < 64) { sums[tid] = 0.f; sumsq[tid] = 0.f; }
    __syncthreads();

#pragma unroll
    for (int mt = 0; mt < 2; mt++) {
        float sA = 0.f, qA = 0.f, sB = 0.f, qB = 0.f;
#pragma unroll
        for (int nt = 0; nt < 8; nt++) {
            sA += acc[mt][nt][0] + acc[mt][nt][1];
            qA += acc[mt][nt][0] * acc[mt][nt][0] + acc[mt][nt][1] * acc[mt][nt][1];
            sB += acc[mt][nt][2] + acc[mt][nt][3];
            qB += acc[mt][nt][2] * acc[mt][nt][2] + acc[mt][nt][3] * acc[mt][nt][3];
        }
        sA += __shfl_xor_sync(0xffffffffu, sA, 1); sA += __shfl_xor_sync(0xffffffffu, sA, 2);
        qA += __shfl_xor_sync(0xffffffffu, qA, 1); qA += __shfl_xor_sync(0xffffffffu, qA, 2);
        sB += __shfl_xor_sync(0xffffffffu, sB, 1); sB += __shfl_xor_sync(0xffffffffu, sB, 2);
        qB += __shfl_xor_sync(0xffffffffu, qB, 1); qB += __shfl_xor_sync(0xffffffffu, qB, 2);
        if (tig == 0) {
            const int lr = wm + mt * 16 + gid;
            atomicAdd(&sums[lr], sA);     atomicAdd(&sumsq[lr], qA);
            atomicAdd(&sums[lr + 8], sB); atomicAdd(&sumsq[lr + 8], qB);
        }
    }
    __syncthreads();

    const float inv = 1.f / 256.f;
#pragma unroll
    for (int mt = 0; mt < 2; mt++) {
        const int lr0 = wm + mt * 16 + gid;
        const int lr1 = lr0 + 8;
        const float mu0 = sums[lr0] * inv;
        const float mu1 = sums[lr1] * inv;
        const float rs0 = rsqrtf(sumsq[lr0] * inv - mu0 * mu0 + EPSv);
        const float rs1 = rsqrtf(sumsq[lr1] * inv - mu1 * mu1 + EPSv);
        const int r0 = bm + lr0, r1 = bm + lr1;
#pragma unroll
        for (int nt = 0; nt < 8; nt++) {
            const int col = wn + nt * 8 + 2 * tig;
            float2 gv = *reinterpret_cast<const float2*>(&lng[col]);
            float2 bv = *reinterpret_cast<const float2*>(&lnb[col]);
            float2 o0 = make_float2((acc[mt][nt][0] - mu0) * rs0 * gv.x + bv.x,
                                    (acc[mt][nt][1] - mu0) * rs0 * gv.y + bv.y);
            float2 o1 = make_float2((acc[mt][nt][2] - mu1) * rs1 * gv.x + bv.x,
                                    (acc[mt][nt][3] - mu1) * rs1 * gv.y + bv.y);
            *reinterpret_cast<float2*>(&C[(size_t)r0 * 256 + col]) = o0;
            *reinterpret_cast<float2*>(&C[(size_t)r1 * 256 + col]) = o1;
            if (C2) {
                *reinterpret_cast<__half2*>(&C2[(size_t)r0 * 256 + col]) =
                    __floats2half2_rn(o0.x, o0.y);
                *reinterpret_cast<__half2*>(&C2[(size_t)r1 * 256 + col]) =
                    __floats2half2_rn(o1.x, o1.y);
            }
        }
    }
}

// ------------------------- CSR build ----------------------------------------------
__global__ void hist_kernel(const int* __restrict__ dst, int* __restrict__ cnt, int E)
{
    int e = blockIdx.x * blockDim.x + threadIdx.x;
    if (e < E) atomicAdd(&cnt[dst[e]], 1);
}

__global__ __launch_bounds__(1024) void scan64k(
    const int* __restrict__ cnt, int* __restrict__ rowptr, int* __restrict__ wr)
{
    __shared__ int ss[1024];
    const int tid = threadIdx.x;
    const int base = tid * 64;
    int s = 0;
#pragma unroll
    for (int i = 0; i < 64; i++) s += cnt[base + i];
    ss[tid] = s;
    __syncthreads();
#pragma unroll
    for (int off = 1; off < 1024; off <<= 1) {
        int t = (tid >= off) ? ss[tid - off] : 0;
        __syncthreads();
        ss[tid] += t;
        __syncthreads();
    }
    int run = ss[tid] - s;
    for (int i = 0; i < 64; i++) {
        rowptr[base + i] = run;
        wr[base + i] = run;
        run += cnt[base + i];
    }
    if (tid == 1023) rowptr[NN] = run;
}

__global__ void scatter_csr(const int* __restrict__ src, const int* __restrict__ dst,
                            const int* __restrict__ et, int* __restrict__ wr,
                            int* __restrict__ srcs, int* __restrict__ ets, int E)
{
    int e = blockIdx.x * blockDim.x + threadIdx.x;
    if (e >= E) return;
    int pos = atomicAdd(&wr[dst[e]], 1);
    srcs[pos] = src[e];
    if (et) ets[pos] = et[e];
}

// ------------------------- per-destination attention (fp16 k/v + ak) --------------
template<bool HASAK>
__global__ void dst_attn(const float* __restrict__ q, const __half* __restrict__ kv,
                         const __half* __restrict__ akh,
                         const int* __restrict__ srcs, const int* __restrict__ ets,
                         const int* __restrict__ rowptr, __half* __restrict__ agg)
{
    const int node = (blockIdx.x * blockDim.x + threadIdx.x) >> 5;
    const int lane = threadIdx.x & 31;
    const float4* qr = reinterpret_cast<const float4*>(q + (size_t)node * 256);
    float4 q0 = qr[lane * 2], q1 = qr[lane * 2 + 1];
    const int beg = rowptr[node], end = rowptr[node + 1];

    float4 acc0 = make_float4(0.f, 0.f, 0.f, 0.f);
    float4 acc1 = make_float4(0.f, 0.f, 0.f, 0.f);
    float den = 0.f;

#pragma unroll 4
    for (int j = beg; j < end; j++) {
        const int s = srcs[j];
        const __half* kvrow = kv + (size_t)s * 512;
        uint4 kraw = *reinterpret_cast<const uint4*>(kvrow + lane * 8);
        const __half2* kh = reinterpret_cast<const __half2*>(&kraw);
        float2 kA = __half22float2(kh[0]);
        float2 kB = __half22float2(kh[1]);
        float2 kC = __half22float2(kh[2]);
        float2 kD = __half22float2(kh[3]);
        if (HASAK) {
            uint4 araw = *reinterpret_cast<const uint4*>(
                akh + (size_t)ets[j] * DKK + (lane & 3) * 8);
            const __half2* ah = reinterpret_cast<const __half2*>(&araw);
            float2 aA = __half22float2(ah[0]);
            float2 aB = __half22float2(ah[1]);
            float2 aC = __half22float2(ah[2]);
            float2 aD = __half22float2(ah[3]);
            kA.x += aA.x; kA.y += aA.y; kB.x += aB.x; kB.y += aB.y;
            kC.x += aC.x; kC.y += aC.y; kD.x += aD.x; kD.y += aD.y;
        }
        float p = kA.x * q0.x + kA.y * q0.y + kB.x * q0.z + kB.y * q0.w
                + kC.x * q1.x + kC.y * q1.y + kD.x * q1.z + kD.y * q1.w;
        p += __shfl_xor_sync(0xffffffffu, p, 1);
        p += __shfl_xor_sync(0xffffffffu, p, 2);
        const float w = __expf(p * SCALEv);
        uint4 vraw = *reinterpret_cast<const uint4*>(kvrow + 256 + lane * 8);
        const __half2* vh = reinterpret_cast<const __half2*>(&vraw);
        float2 vA = __half22float2(vh[0]);
        float2 vB = __half22float2(vh[1]);
        float2 vC = __half22float2(vh[2]);
        float2 vD = __half22float2(vh[3]);
        acc0.x += w * vA.x; acc0.y += w * vA.y; acc0.z += w * vB.x; acc0.w += w * vB.y;
        acc1.x += w * vC.x; acc1.y += w * vC.y; acc1.z += w * vD.x; acc1.w += w * vD.y;
        den += w;
    }
    const float r = den > 0.f ? __frcp_rn(den) : 0.f;
    __half2* outp = reinterpret_cast<__half2*>(agg + (size_t)node * DD + lane * 8);
    outp[0] = __floats2half2_rn(acc0.x * r, acc0.y * r);
    outp[1] = __floats2half2_rn(acc0.z * r, acc0.w * r);
    outp[2] = __floats2half2_rn(acc1.x * r, acc1.y * r);
    outp[3] = __floats2half2_rn(acc1.z * r, acc1.w * r);
}

// ------------------------- host launch -------------------------
extern "C" void kernel_launch(void* const* d_in, const int* in_sizes, int n_in,
                              void* d_out, int out_size)
{
    const float *h = nullptr, *mem = nullptr, *ak = nullptr, *bf1 = nullptr;
    const float *W[8] = {nullptr};
    const float *Wf[2] = {nullptr};
    const float *v256[8] = {nullptr};
    const int *src_intra = nullptr, *dst_intra = nullptr, *etype = nullptr;
    const int *src_inter = nullptr, *dst_inter = nullptr;
    int c16 = 0, c1m = 0, c512k = 0, c64k = 0, c262k = 0, c256 = 0;

    for (int i = 0; i < n_in; i++) {
        int sz = in_sizes[i];
        void* p = d_in[i];
        if (sz == 16777216)      { if (c16 == 0) h = (const float*)p; else mem = (const float*)p; c16++; }
        else if (sz == 1048576)  { if (c1m == 0) src_intra = (const int*)p;
                                   else if (c1m == 1) dst_intra = (const int*)p;
                                   else etype = (const int*)p; c1m++; }
        else if (sz == 524288)   { if (c512k == 0) src_inter = (const int*)p; else dst_inter = (const int*)p; c512k++; }
        else if (sz == 65536)    { if (c64k < 8) W[c64k] = (const float*)p; c64k++; }
        else if (sz == 32000)    { ak = (const float*)p; }
        else if (sz == 262144)   { if (c262k < 2) Wf[c262k] = (const float*)p; c262k++; }
        else if (sz == 1024)     { bf1 = (const float*)p; }
        else if (sz == 256)      { if (c256 < 8) v256[c256] = (const float*)p; c256++; }
    }
    const float *ln0_g = v256[0], *ln0_b = v256[1];
    const float *ln1_g = v256[2], *ln1_b = v256[3];
    const float *ln2_g = v256[4], *ln2_b = v256[5];
    const float *bf2   = v256[6];

    float *q, *q2, *h1;
    __half *kv, *kv2, *akh, *agg, *h1r, *hr, *memr, *ffn;
    __half *wqkv0, *wqkv1, *wo0r, *wo1r, *wf1r, *wf2r;
    int *cnt, *wr, *rowptr, *srcs, *ets;
    int *cnt2, *wr2, *rowptr2, *srcs2;
    cudaGetSymbolAddress((void**)&q,      g_q);
    cudaGetSymbolAddress((void**)&q2,     g_q2);
    cudaGetSymbolAddress((void**)&kv,     g_kv);
    cudaGetSymbolAddress((void**)&kv2,    g_kv2);
    cudaGetSymbolAddress((void**)&akh,    g_akh);
    cudaGetSymbolAddress((void**)&agg,    g_agg);
    cudaGetSymbolAddress((void**)&h1,     g_h1);
    cudaGetSymbolAddress((void**)&h1r,    g_h1r);
    cudaGetSymbolAddress((void**)&hr,     g_hr);
    cudaGetSymbolAddress((void**)&memr,   g_memr);
    cudaGetSymbolAddress((void**)&ffn,    g_ffn);
    cudaGetSymbolAddress((void**)&wqkv0,  g_wqkv0);
    cudaGetSymbolAddress((void**)&wqkv1,  g_wqkv1);
    cudaGetSymbolAddress((void**)&wo0r,   g_wo0r);
    cudaGetSymbolAddress((void**)&wo1r,   g_wo1r);
    cudaGetSymbolAddress((void**)&wf1r,   g_wf1r);
    cudaGetSymbolAddress((void**)&wf2r,   g_wf2r);
    cudaGetSymbolAddress((void**)&cnt,    g_cnt);
    cudaGetSymbolAddress((void**)&wr,     g_wr);
    cudaGetSymbolAddress((void**)&rowptr, g_rowptr);
    cudaGetSymbolAddress((void**)&srcs,   g_srcs);
    cudaGetSymbolAddress((void**)&ets,    g_ets);
    cudaGetSymbolAddress((void**)&cnt2,   g_cnt2);
    cudaGetSymbolAddress((void**)&wr2,    g_wr2);
    cudaGetSymbolAddress((void**)&rowptr2,g_rowptr2);
    cudaGetSymbolAddress((void**)&srcs2,  g_srcs2);

    float* out = (float*)d_out;

    cudaFuncSetAttribute(gemmA4,   cudaFuncAttributeMaxDynamicSharedMemorySize, SMEM_A);
    cudaFuncSetAttribute(gemm_q4,  cudaFuncAttributeMaxDynamicSharedMemorySize, SMEM_A);
    cudaFuncSetAttribute(gemm_kv4, cudaFuncAttributeMaxDynamicSharedMemorySize, SMEM_A);
    cudaFuncSetAttribute(gemmB_ln, cudaFuncAttributeMaxDynamicSharedMemorySize, SMEM_B);

    // ---------------- stream fork ----------------
    cudaStream_t s2;
    cudaStreamCreateWithFlags(&s2, cudaStreamNonBlocking);
    cudaEvent_t evRoot, evPrep, evCSR1, evS2;
    cudaEventCreateWithFlags(&evRoot, cudaEventDisableTiming);
    cudaEventCreateWithFlags(&evPrep, cudaEventDisableTiming);
    cudaEventCreateWithFlags(&evCSR1, cudaEventDisableTiming);
    cudaEventCreateWithFlags(&evS2,   cudaEventDisableTiming);

    cudaEventRecord(evRoot, 0);
    cudaStreamWaitEvent(s2, evRoot, 0);

    // side stream: both CSR builds
    cudaMemsetAsync(cnt,  0, NN * sizeof(int), s2);
    cudaMemsetAsync(cnt2, 0, NN * sizeof(int), s2);
    hist_kernel<<<E1v / 256, 256, 0, s2>>>(dst_intra, cnt, E1v);
    scan64k<<<1, 1024, 0, s2>>>(cnt, rowptr, wr);
    scatter_csr<<<E1v / 256, 256, 0, s2>>>(src_intra, dst_intra, etype, wr, srcs, ets, E1v);
    cudaEventRecord(evCSR1, s2);
    hist_kernel<<<E2v / 256, 256, 0, s2>>>(dst_inter, cnt2, E2v);
    scan64k<<<1, 1024, 0, s2>>>(cnt2, rowptr2, wr2);
    scatter_csr<<<E2v / 256, 256, 0, s2>>>(src_inter, dst_inter, nullptr, wr2, srcs2, nullptr, E2v);

    // main stream: prep
    pack_ak<<<125, 256>>>(ak, akh);
    pack_qkv_b_h<<<DD * QKVS / 256, 256>>>(W[0], W[1], W[2], wqkv0);
    pack_qkv_b_h<<<DD * QKVS / 256, 256>>>(W[4], W[5], W[6], wqkv1);
    pack_b_h<<<DD * DD / 256, 256>>>(W[3], wo0r, DD, DD);
    pack_b_h<<<DD * DD / 256, 256>>>(W[7], wo1r, DD, DD);
    pack_b_h<<<DD * DFFv / 256, 256>>>(Wf[0], wf1r, DD, DFFv);
    pack_b_h<<<DFFv * DD / 256, 256>>>(Wf[1], wf2r, DFFv, DD);
    round_half<<<NN * DD / 4 / 256, 256>>>(h, hr);
    round_half<<<NN * DD / 4 / 256, 256>>>(mem, memr);
    cudaEventRecord(evPrep, 0);
    cudaStreamWaitEvent(s2, evPrep, 0);

    // side stream: stage-2 K/V projection (independent of stage 1)
    gemm_kv4<<<dim3(4, NN / 128), 128, SMEM_A, s2>>>(memr, wqkv1, kv2);
    cudaEventRecord(evS2, s2);

    dim3 gLN(1, NN / 64);
    dim3 gF1(DFFv / 128, NN / 128);
    const int ATT_BLKS = NN / 8;

    // ---------------- stage 1: intra attention ----------------
    gemm_q4 <<<dim3(2, NN / 128), 128, SMEM_A>>>(hr, wqkv0, q);
    gemm_kv4<<<dim3(4, NN / 128), 128, SMEM_A>>>(hr, wqkv0, kv);
    cudaStreamWaitEvent(0, evCSR1, 0);
    dst_attn<true><<<ATT_BLKS, 256>>>(q, kv, akh, srcs, ets, rowptr, agg);
    gemmB_ln<<<gLN, 256, SMEM_B>>>(agg, wo0r, h1, DD, nullptr, h, ln0_g, ln0_b, h1r);

    // ---------------- stage 2: inter attention ----------------
    gemm_q4<<<dim3(2, NN / 128), 128, SMEM_A>>>(h1r, wqkv1, q2);
    cudaStreamWaitEvent(0, evS2, 0);
    dst_attn<false><<<ATT_BLKS, 256>>>(q2, kv2, nullptr, srcs2, nullptr, rowptr2, agg);
    gemmB_ln<<<gLN, 256, SMEM_B>>>(agg, wo1r, h1, DD, nullptr, h1, ln1_g, ln1_b, h1r);

    // ---------------- FFN + final norm ----------------
    gemmA4<<<gF1, 128, SMEM_A>>>(h1r, wf1r, ffn, DD, DFFv, bf1);
    gemmB_ln<<<gLN, 256, SMEM_B>>>(ffn, wf2r, out, DFFv, bf2, h1, ln2_g, ln2_b, nullptr);
}